// round 12
// baseline (speedup 1.0000x reference)
#include <cuda_runtime.h>
#include <cstdint>

#define CDIM 256
#define NDIM 512
#define TM   32
#define NTH  256
#define KITER 15
#define ATS  36                    // a_t padded row stride (floats)
#define ATFLOATS (NDIM * ATS)      // 18432 floats
#define CES  34                    // ceff padded col stride (floats, even for u64 align)

typedef unsigned long long u64;

// Device-global scratch (allocation-free), value-duplicated weight layouts.
__device__ float g_Wsd[NDIM * 2 * NDIM];     // [k=512][1024]  dup symmetrized W
__device__ float g_WinTd[CDIM * 2 * NDIM];   // [k=256][1024]  dup W_in^T
__device__ float g_WoutTd[NDIM * 2 * CDIM];  // [k=512][512]   dup W_out^T

// ---------- packed f32x2 helpers ----------
__device__ __forceinline__ u64 pack2(float lo, float hi) {
    u64 r; asm("mov.b64 %0,{%1,%2};" : "=l"(r) : "f"(lo), "f"(hi)); return r;
}
__device__ __forceinline__ float2 unpack2(u64 v) {
    float2 f; asm("mov.b64 {%0,%1},%2;" : "=f"(f.x), "=f"(f.y) : "l"(v)); return f;
}
__device__ __forceinline__ u64 fma2(u64 a, u64 b, u64 c) {
    u64 d; asm("fma.rn.f32x2 %0,%1,%2,%3;" : "=l"(d) : "l"(a), "l"(b), "l"(c)); return d;
}
__device__ __forceinline__ u64 add2(u64 a, u64 b) {
    u64 d; asm("add.rn.f32x2 %0,%1,%2;" : "=l"(d) : "l"(a), "l"(b)); return d;
}
__device__ __forceinline__ float tanh_fast(float v) {
    float r; asm("tanh.approx.f32 %0,%1;" : "=f"(r) : "f"(v)); return r;
}
__device__ __forceinline__ float tanh_accurate(float v) {
    float e = __expf(2.0f * v);
    return 1.0f - 2.0f / (e + 1.0f);
}

// ---------- per-warp GEMM streaming W straight from L2 via LDG ----------
// acc[p][c]: row-pair p (rows 2p,2p+1) packed f32x2; c = lane-local column.
// gw: this lane's slice in the dup weight matrix (row stride ROWF floats).
// NC==2: one LDG.128 per k yields (w0,w0),(w1,w1).  NC==1: one LDG.64.
template <int K, int NC, int ROWF>
__device__ __forceinline__ void stream_gemm_ldg(const float* __restrict__ gw,
                                                const float* __restrict__ a_t,
                                                u64 (&acc)[16][NC]) {
    constexpr int PF = 4;                 // prefetch depth (registers)
    u64 wbuf[PF][NC];
#pragma unroll
    for (int i = 0; i < PF; i++) {
        if (NC == 2) {
            ulonglong2 t = *(const ulonglong2*)(gw + (long)i * ROWF);
            wbuf[i][0] = t.x; wbuf[i][NC - 1] = t.y;
        } else {
            wbuf[i][0] = *(const u64*)(gw + (long)i * ROWF);
        }
    }
#pragma unroll 1
    for (int kb = 0; kb < K; kb += PF) {
#pragma unroll
        for (int kk = 0; kk < PF; kk++) {
            const int k = kb + kk;
            u64 w0 = wbuf[kk][0];
            u64 w1 = wbuf[kk][NC - 1];
            // prefetch k+PF (clamped in-bounds; garbage value never used)
            long knext = (k + PF < K) ? (k + PF) : k;
            if (NC == 2) {
                ulonglong2 t = *(const ulonglong2*)(gw + knext * ROWF);
                wbuf[kk][0] = t.x; wbuf[kk][NC - 1] = t.y;
            } else {
                wbuf[kk][0] = *(const u64*)(gw + knext * ROWF);
            }
            // a column vector (32 rows = 16 f32x2), broadcast LDS.128
            const ulonglong2* ap = (const ulonglong2*)(a_t + k * ATS);
            u64 a8[16];
#pragma unroll
            for (int q = 0; q < 8; q++) { ulonglong2 t = ap[q]; a8[2*q] = t.x; a8[2*q+1] = t.y; }
            if (NC == 2) {
#pragma unroll
                for (int p = 0; p < 16; p++) {
                    acc[p][0]      = fma2(a8[p], w0, acc[p][0]);
                    acc[p][NC - 1] = fma2(a8[p], w1, acc[p][NC - 1]);
                }
            } else {
#pragma unroll
                for (int p = 0; p < 16; p++) acc[p][0] = fma2(a8[p], w0, acc[p][0]);
            }
        }
    }
}

// ---------- prep: build duplicated weight layouts ----------
__global__ void prep_kernel(const float* __restrict__ W_in,
                            const float* __restrict__ W,
                            const float* __restrict__ W_out) {
    int i = blockIdx.x * blockDim.x + threadIdx.x;
    if (i < NDIM * NDIM) {
        int k = i >> 9, n = i & 511;
        float v = 0.5f * (W[i] + W[n * NDIM + k]);
        g_Wsd[k * 1024 + 2 * n] = v; g_Wsd[k * 1024 + 2 * n + 1] = v;
    }
    if (i < CDIM * NDIM) {
        int k = i >> 9, n = i & 511;
        float v = W_in[n * CDIM + k];
        g_WinTd[k * 1024 + 2 * n] = v; g_WinTd[k * 1024 + 2 * n + 1] = v;
    }
    if (i < NDIM * CDIM) {
        int k = i >> 8, j = i & 255;
        float v = W_out[j * NDIM + k];
        g_WoutTd[k * 512 + 2 * j] = v; g_WoutTd[k * 512 + 2 * j + 1] = v;
    }
}

// ---------- fused attractor kernel ----------
__global__ void __launch_bounds__(NTH, 1)
attractor_kernel(const float* __restrict__ x, const float* __restrict__ b_in,
                 const float* __restrict__ bvec, const float* __restrict__ b_out,
                 float* __restrict__ y) {
    extern __shared__ float smem[];
    float* a_t     = smem;                  // [512 k][32 rows], stride ATS
    float* ceff_sm = smem + ATFLOATS;       // [512 cols][32 rows], stride CES

    const int tid  = threadIdx.x;
    const int wid  = tid >> 5;
    const int lane = tid & 31;
    const long row0 = (long)blockIdx.x * TM;
    const int c0 = 64 * wid + 2 * lane;     // this lane's 2 columns

    // ===== stage x transposed into a_t (tid = channel) =====
#pragma unroll 4
    for (int r = 0; r < TM; r++)
        a_t[tid * ATS + r] = x[(row0 + r) * CDIM + tid];
    __syncthreads();

    u64 acc[16][2];

    // ===== Phase A: c = x @ W_in^T (K=256); fold biases; stash ceff in smem =====
#pragma unroll
    for (int p = 0; p < 16; p++) { acc[p][0] = 0ull; acc[p][1] = 0ull; }
    stream_gemm_ldg<CDIM, 2, 1024>(g_WinTd + wid * 128 + lane * 4, a_t, acc);
    {
        u64 bb0 = pack2(b_in[c0] + bvec[c0], b_in[c0] + bvec[c0]);
        u64 bb1 = pack2(b_in[c0+1] + bvec[c0+1], b_in[c0+1] + bvec[c0+1]);
#pragma unroll
        for (int p = 0; p < 16; p++) {
            acc[p][0] = add2(acc[p][0], bb0);
            acc[p][1] = add2(acc[p][1], bb1);
            *(u64*)(ceff_sm + c0 * CES + 2 * p)       = acc[p][0];
            *(u64*)(ceff_sm + (c0 + 1) * CES + 2 * p) = acc[p][1];
        }
    }

    // ===== iteration 1: a1 = tanh(ceff)  (a0 = 0, GEMM skipped) =====
    __syncthreads();    // all warps done reading x from a_t
#pragma unroll
    for (int c = 0; c < 2; c++) {
        float v[32];
#pragma unroll
        for (int p = 0; p < 16; p++) {
            float2 f = unpack2(acc[p][c]);
            v[2*p] = tanh_fast(f.x); v[2*p+1] = tanh_fast(f.y);
        }
        float* dst = a_t + (c0 + c) * ATS;
#pragma unroll
        for (int q = 0; q < 8; q++)
            *(float4*)(dst + 4*q) = make_float4(v[4*q], v[4*q+1], v[4*q+2], v[4*q+3]);
    }
    __syncthreads();

    // ===== iterations 2..15: a = tanh(a @ Ws + ceff) =====
#pragma unroll 1
    for (int t = 0; t < KITER - 1; t++) {
        const bool last = (t == KITER - 2);
#pragma unroll
        for (int p = 0; p < 16; p++) {
            acc[p][0] = *(const u64*)(ceff_sm + c0 * CES + 2 * p);
            acc[p][1] = *(const u64*)(ceff_sm + (c0 + 1) * CES + 2 * p);
        }

        stream_gemm_ldg<NDIM, 2, 1024>(g_Wsd + wid * 128 + lane * 4, a_t, acc);

        __syncthreads();    // all warps done reading a_t
#pragma unroll
        for (int c = 0; c < 2; c++) {
            float v[32];
#pragma unroll
            for (int p = 0; p < 16; p++) {
                float2 f = unpack2(acc[p][c]);
                if (last) { v[2*p] = tanh_accurate(f.x); v[2*p+1] = tanh_accurate(f.y); }
                else      { v[2*p] = tanh_fast(f.x);     v[2*p+1] = tanh_fast(f.y); }
            }
            float* dst = a_t + (c0 + c) * ATS;
#pragma unroll
            for (int q = 0; q < 8; q++)
                *(float4*)(dst + 4*q) = make_float4(v[4*q], v[4*q+1], v[4*q+2], v[4*q+3]);
        }
        __syncthreads();
    }

    // ===== Phase C: y = a @ W_out^T + b_out  (1 output col per lane) =====
    {
        const int col = 32 * wid + lane;
        u64 oacc[16][1];
        float bo = b_out[col];
#pragma unroll
        for (int p = 0; p < 16; p++) oacc[p][0] = pack2(bo, bo);

        stream_gemm_ldg<NDIM, 1, 512>(g_WoutTd + wid * 64 + lane * 2, a_t, oacc);

        __syncthreads();    // all warps done reading a_t; reuse as y staging
#pragma unroll
        for (int p = 0; p < 16; p++)
            *(u64*)(a_t + col * ATS + 2 * p) = oacc[p][0];
        __syncthreads();

#pragma unroll 4
        for (int r = 0; r < TM; r++)
            y[(row0 + r) * CDIM + tid] = a_t[tid * ATS + r];
    }
}

extern "C" void kernel_launch(void* const* d_in, const int* in_sizes, int n_in,
                              void* d_out, int out_size) {
    const float* x     = (const float*)d_in[0];
    const float* W_in  = (const float*)d_in[1];
    const float* b_in  = (const float*)d_in[2];
    const float* W     = (const float*)d_in[3];
    const float* bvec  = (const float*)d_in[4];
    const float* W_out = (const float*)d_in[5];
    const float* b_out = (const float*)d_in[6];
    float* y = (float*)d_out;

    const int rows = in_sizes[0] / CDIM;            // 65536
    const int nblk = rows / TM;                     // 2048
    const int smem_bytes = (ATFLOATS + NDIM * CES) * 4;  // 73728 + 69632 = 143360

    cudaFuncSetAttribute(attractor_kernel,
                         cudaFuncAttributeMaxDynamicSharedMemorySize, smem_bytes);

    prep_kernel<<<1024, 256>>>(W_in, W, W_out);
    attractor_kernel<<<nblk, NTH, smem_bytes>>>(x, b_in, bvec, b_out, y);
}

// round 13
// speedup vs baseline: 1.0003x; 1.0003x over previous
#include <cuda_runtime.h>
#include <cstdint>

#define CDIM 256
#define NDIM 512
#define TM   32
#define NTH  256
#define KITER 15
#define ATS  36                    // a_t padded row stride (floats)
#define ATFLOATS (NDIM * ATS)      // 18432 floats
#define CES  34                    // ceff padded col stride (floats, even for u64 align)

typedef unsigned long long u64;

// Device-global scratch (allocation-free), value-duplicated weight layouts.
__device__ float g_Wsd[NDIM * 2 * NDIM];     // [k=512][1024]  dup symmetrized W
__device__ float g_WinTd[CDIM * 2 * NDIM];   // [k=256][1024]  dup W_in^T
__device__ float g_WoutTd[NDIM * 2 * CDIM];  // [k=512][512]   dup W_out^T

// ---------- packed f32x2 helpers ----------
__device__ __forceinline__ u64 pack2(float lo, float hi) {
    u64 r; asm("mov.b64 %0,{%1,%2};" : "=l"(r) : "f"(lo), "f"(hi)); return r;
}
__device__ __forceinline__ float2 unpack2(u64 v) {
    float2 f; asm("mov.b64 {%0,%1},%2;" : "=f"(f.x), "=f"(f.y) : "l"(v)); return f;
}
__device__ __forceinline__ u64 fma2(u64 a, u64 b, u64 c) {
    u64 d; asm("fma.rn.f32x2 %0,%1,%2,%3;" : "=l"(d) : "l"(a), "l"(b), "l"(c)); return d;
}
__device__ __forceinline__ u64 add2(u64 a, u64 b) {
    u64 d; asm("add.rn.f32x2 %0,%1,%2;" : "=l"(d) : "l"(a), "l"(b)); return d;
}
__device__ __forceinline__ float tanh_fast(float v) {
    float r; asm("tanh.approx.f32 %0,%1;" : "=f"(r) : "f"(v)); return r;
}
__device__ __forceinline__ float tanh_accurate(float v) {
    float e = __expf(2.0f * v);
    return 1.0f - 2.0f / (e + 1.0f);
}

// ---------- per-warp GEMM streaming W straight from L2 via LDG ----------
// acc[p][c]: row-pair p (rows 2p,2p+1) packed f32x2; c = lane-local column.
// gw: this lane's slice in the dup weight matrix (row stride ROWF floats).
// NC==2: one LDG.128 per k yields (w0,w0),(w1,w1).  NC==1: one LDG.64.
template <int K, int NC, int ROWF>
__device__ __forceinline__ void stream_gemm_ldg(const float* __restrict__ gw,
                                                const float* __restrict__ a_t,
                                                u64 (&acc)[16][NC]) {
    constexpr int PF = 4;                 // prefetch depth (registers)
    u64 wbuf[PF][NC];
#pragma unroll
    for (int i = 0; i < PF; i++) {
        if (NC == 2) {
            ulonglong2 t = *(const ulonglong2*)(gw + (long)i * ROWF);
            wbuf[i][0] = t.x; wbuf[i][NC - 1] = t.y;
        } else {
            wbuf[i][0] = *(const u64*)(gw + (long)i * ROWF);
        }
    }
#pragma unroll 1
    for (int kb = 0; kb < K; kb += PF) {
#pragma unroll
        for (int kk = 0; kk < PF; kk++) {
            const int k = kb + kk;
            u64 w0 = wbuf[kk][0];
            u64 w1 = wbuf[kk][NC - 1];
            // prefetch k+PF (clamped in-bounds; garbage value never used)
            long knext = (k + PF < K) ? (k + PF) : k;
            if (NC == 2) {
                ulonglong2 t = *(const ulonglong2*)(gw + knext * ROWF);
                wbuf[kk][0] = t.x; wbuf[kk][NC - 1] = t.y;
            } else {
                wbuf[kk][0] = *(const u64*)(gw + knext * ROWF);
            }
            // a column vector (32 rows = 16 f32x2), broadcast LDS.128
            const ulonglong2* ap = (const ulonglong2*)(a_t + k * ATS);
            u64 a8[16];
#pragma unroll
            for (int q = 0; q < 8; q++) { ulonglong2 t = ap[q]; a8[2*q] = t.x; a8[2*q+1] = t.y; }
            if (NC == 2) {
#pragma unroll
                for (int p = 0; p < 16; p++) {
                    acc[p][0]      = fma2(a8[p], w0, acc[p][0]);
                    acc[p][NC - 1] = fma2(a8[p], w1, acc[p][NC - 1]);
                }
            } else {
#pragma unroll
                for (int p = 0; p < 16; p++) acc[p][0] = fma2(a8[p], w0, acc[p][0]);
            }
        }
    }
}

// ---------- prep: build duplicated weight layouts ----------
__global__ void prep_kernel(const float* __restrict__ W_in,
                            const float* __restrict__ W,
                            const float* __restrict__ W_out) {
    int i = blockIdx.x * blockDim.x + threadIdx.x;
    if (i < NDIM * NDIM) {
        int k = i >> 9, n = i & 511;
        float v = 0.5f * (W[i] + W[n * NDIM + k]);
        g_Wsd[k * 1024 + 2 * n] = v; g_Wsd[k * 1024 + 2 * n + 1] = v;
    }
    if (i < CDIM * NDIM) {
        int k = i >> 9, n = i & 511;
        float v = W_in[n * CDIM + k];
        g_WinTd[k * 1024 + 2 * n] = v; g_WinTd[k * 1024 + 2 * n + 1] = v;
    }
    if (i < NDIM * CDIM) {
        int k = i >> 8, j = i & 255;
        float v = W_out[j * NDIM + k];
        g_WoutTd[k * 512 + 2 * j] = v; g_WoutTd[k * 512 + 2 * j + 1] = v;
    }
}

// ---------- fused attractor kernel ----------
__global__ void __launch_bounds__(NTH, 1)
attractor_kernel(const float* __restrict__ x, const float* __restrict__ b_in,
                 const float* __restrict__ bvec, const float* __restrict__ b_out,
                 float* __restrict__ y) {
    extern __shared__ float smem[];
    float* a_t     = smem;                  // [512 k][32 rows], stride ATS
    float* ceff_sm = smem + ATFLOATS;       // [512 cols][32 rows], stride CES

    const int tid  = threadIdx.x;
    const int wid  = tid >> 5;
    const int lane = tid & 31;
    const long row0 = (long)blockIdx.x * TM;
    const int c0 = 64 * wid + 2 * lane;     // this lane's 2 columns

    // ===== stage x transposed into a_t (tid = channel) =====
#pragma unroll 4
    for (int r = 0; r < TM; r++)
        a_t[tid * ATS + r] = x[(row0 + r) * CDIM + tid];
    __syncthreads();

    u64 acc[16][2];

    // ===== Phase A: c = x @ W_in^T (K=256); fold biases; stash ceff in smem =====
#pragma unroll
    for (int p = 0; p < 16; p++) { acc[p][0] = 0ull; acc[p][1] = 0ull; }
    stream_gemm_ldg<CDIM, 2, 1024>(g_WinTd + wid * 128 + lane * 4, a_t, acc);
    {
        u64 bb0 = pack2(b_in[c0] + bvec[c0], b_in[c0] + bvec[c0]);
        u64 bb1 = pack2(b_in[c0+1] + bvec[c0+1], b_in[c0+1] + bvec[c0+1]);
#pragma unroll
        for (int p = 0; p < 16; p++) {
            acc[p][0] = add2(acc[p][0], bb0);
            acc[p][1] = add2(acc[p][1], bb1);
            *(u64*)(ceff_sm + c0 * CES + 2 * p)       = acc[p][0];
            *(u64*)(ceff_sm + (c0 + 1) * CES + 2 * p) = acc[p][1];
        }
    }

    // ===== iteration 1: a1 = tanh(ceff)  (a0 = 0, GEMM skipped) =====
    __syncthreads();    // all warps done reading x from a_t
#pragma unroll
    for (int c = 0; c < 2; c++) {
        float v[32];
#pragma unroll
        for (int p = 0; p < 16; p++) {
            float2 f = unpack2(acc[p][c]);
            v[2*p] = tanh_fast(f.x); v[2*p+1] = tanh_fast(f.y);
        }
        float* dst = a_t + (c0 + c) * ATS;
#pragma unroll
        for (int q = 0; q < 8; q++)
            *(float4*)(dst + 4*q) = make_float4(v[4*q], v[4*q+1], v[4*q+2], v[4*q+3]);
    }
    __syncthreads();

    // ===== iterations 2..15: a = tanh(a @ Ws + ceff) =====
#pragma unroll 1
    for (int t = 0; t < KITER - 1; t++) {
        const bool last = (t == KITER - 2);
#pragma unroll
        for (int p = 0; p < 16; p++) {
            acc[p][0] = *(const u64*)(ceff_sm + c0 * CES + 2 * p);
            acc[p][1] = *(const u64*)(ceff_sm + (c0 + 1) * CES + 2 * p);
        }

        stream_gemm_ldg<NDIM, 2, 1024>(g_Wsd + wid * 128 + lane * 4, a_t, acc);

        __syncthreads();    // all warps done reading a_t
#pragma unroll
        for (int c = 0; c < 2; c++) {
            float v[32];
#pragma unroll
            for (int p = 0; p < 16; p++) {
                float2 f = unpack2(acc[p][c]);
                if (last) { v[2*p] = tanh_accurate(f.x); v[2*p+1] = tanh_accurate(f.y); }
                else      { v[2*p] = tanh_fast(f.x);     v[2*p+1] = tanh_fast(f.y); }
            }
            float* dst = a_t + (c0 + c) * ATS;
#pragma unroll
            for (int q = 0; q < 8; q++)
                *(float4*)(dst + 4*q) = make_float4(v[4*q], v[4*q+1], v[4*q+2], v[4*q+3]);
        }
        __syncthreads();
    }

    // ===== Phase C: y = a @ W_out^T + b_out  (1 output col per lane) =====
    {
        const int col = 32 * wid + lane;
        u64 oacc[16][1];
        float bo = b_out[col];
#pragma unroll
        for (int p = 0; p < 16; p++) oacc[p][0] = pack2(bo, bo);

        stream_gemm_ldg<NDIM, 1, 512>(g_WoutTd + wid * 64 + lane * 2, a_t, oacc);

        __syncthreads();    // all warps done reading a_t; reuse as y staging
#pragma unroll
        for (int p = 0; p < 16; p++)
            *(u64*)(a_t + col * ATS + 2 * p) = oacc[p][0];
        __syncthreads();

#pragma unroll 4
        for (int r = 0; r < TM; r++)
            y[(row0 + r) * CDIM + tid] = a_t[tid * ATS + r];
    }
}

extern "C" void kernel_launch(void* const* d_in, const int* in_sizes, int n_in,
                              void* d_out, int out_size) {
    const float* x     = (const float*)d_in[0];
    const float* W_in  = (const float*)d_in[1];
    const float* b_in  = (const float*)d_in[2];
    const float* W     = (const float*)d_in[3];
    const float* bvec  = (const float*)d_in[4];
    const float* W_out = (const float*)d_in[5];
    const float* b_out = (const float*)d_in[6];
    float* y = (float*)d_out;

    const int rows = in_sizes[0] / CDIM;            // 65536
    const int nblk = rows / TM;                     // 2048
    const int smem_bytes = (ATFLOATS + NDIM * CES) * 4;  // 73728 + 69632 = 143360

    cudaFuncSetAttribute(attractor_kernel,
                         cudaFuncAttributeMaxDynamicSharedMemorySize, smem_bytes);

    prep_kernel<<<1024, 256>>>(W_in, W, W_out);
    attractor_kernel<<<nblk, NTH, smem_bytes>>>(x, b_in, bvec, b_out, y);
}